// round 9
// baseline (speedup 1.0000x reference)
#include <cuda_runtime.h>

#define N_DIST 1024
#define DIM    128
#define HID    256
#define MAXN   500000
#define NBLK   512
#define GCHUNK 2048
#define NSPLIT 4

// Scratch (no allocations allowed) — fully rewritten every launch.
__device__ int   g_counts[N_DIST * NBLK];   // [d][b]  (hist writes strided, scan reads coalesced)
__device__ int   g_bcursor[NBLK * N_DIST];  // [b][d]  (scan writes strided, scatter reads coalesced)
__device__ int   g_total[N_DIST];
__device__ int   g_offsets[N_DIST + 1];
__device__ int   g_order[MAXN];
__device__ float g_heads[NSPLIT][N_DIST * DIM];  // split partial heads (pre-ReLU)

// ---------------------------------------------------------------- A: per-block histogram
// chunk is a multiple of 4; zone read via int4.
__global__ void __launch_bounds__(256) k_hist(const int4* __restrict__ zone4, int n4, int chunk4) {
    __shared__ int sh[N_DIST];
    int b = blockIdx.x, t = threadIdx.x;
    for (int i = t; i < N_DIST; i += 256) sh[i] = 0;
    __syncthreads();
    int s = b * chunk4, e = min(n4, s + chunk4);
    for (int i = s + t; i < e; i += 256) {
        int4 z = zone4[i];
        atomicAdd(&sh[z.x], 1);
        atomicAdd(&sh[z.y], 1);
        atomicAdd(&sh[z.z], 1);
        atomicAdd(&sh[z.w], 1);
    }
    __syncthreads();
    for (int i = t; i < N_DIST; i += 256)
        g_counts[i * NBLK + b] = sh[i];          // strided write (hidden)
}

// ---------------------------------------------------------------- B: scan over blocks per district
__global__ void __launch_bounds__(NBLK) k_scan_blocks() {
    __shared__ int s[NBLK];
    int d = blockIdx.x, t = threadIdx.x;
    int c = g_counts[d * NBLK + t];              // coalesced read
    s[t] = c;
    __syncthreads();
    for (int off = 1; off < NBLK; off <<= 1) {
        int add = (t >= off) ? s[t - off] : 0;
        __syncthreads();
        s[t] += add;
        __syncthreads();
    }
    g_bcursor[t * N_DIST + d] = s[t] - c;        // strided write (hidden)
    if (t == NBLK - 1) g_total[d] = s[t];
}

// ---------------------------------------------------------------- C: scan districts
__global__ void __launch_bounds__(N_DIST) k_scan() {
    __shared__ int s[N_DIST];
    int t = threadIdx.x;
    int cnt = g_total[t];
    s[t] = cnt;
    __syncthreads();
    for (int off = 1; off < N_DIST; off <<= 1) {
        int add = (t >= off) ? s[t - off] : 0;
        __syncthreads();
        s[t] += add;
        __syncthreads();
    }
    g_offsets[t + 1] = s[t];
    if (t == 0) g_offsets[0] = 0;
}

// ---------------------------------------------------------------- D: scatter (smem atomics only)
__global__ void __launch_bounds__(256) k_scatter(const int4* __restrict__ zone4, int n4, int chunk4) {
    __shared__ int cur[N_DIST];
    int b = blockIdx.x, t = threadIdx.x;
    for (int i = t; i < N_DIST; i += 256)
        cur[i] = g_offsets[i] + g_bcursor[b * N_DIST + i];   // coalesced read
    __syncthreads();
    int s = b * chunk4, e = min(n4, s + chunk4);
    for (int i = s + t; i < e; i += 256) {
        int4 z = zone4[i];
        int i0 = i * 4;
        g_order[atomicAdd(&cur[z.x], 1)] = i0;
        g_order[atomicAdd(&cur[z.y], 1)] = i0 + 1;
        g_order[atomicAdd(&cur[z.z], 1)] = i0 + 2;
        g_order[atomicAdd(&cur[z.w], 1)] = i0 + 3;
    }
}

// ---------------------------------------------------------------- E: gather-sum (split-4)
// 4096 blocks: district d = blockIdx>>2, part h = blockIdx&3. 256 threads = 8 warps,
// each warp reads whole 512B rows via LDG.128, 8 rows in flight per iteration.
__global__ void __launch_bounds__(256) k_gather(const float4* __restrict__ x4) {
    __shared__ int    sh_idx[GCHUNK];
    __shared__ float4 sh_part[8][32];
    int d = blockIdx.x >> 2, h = blockIdx.x & 3;
    int t = threadIdx.x;
    int w = t >> 5, lane = t & 31;
    int s0 = g_offsets[d], e0 = g_offsets[d + 1];
    int cnt0 = e0 - s0;
    int q = (cnt0 + NSPLIT - 1) / NSPLIT;
    int s = s0 + h * q;
    int e = min(e0, s + q);
    int cnt = max(0, e - s);
    float4 acc = make_float4(0.f, 0.f, 0.f, 0.f);

    for (int base = 0; base < cnt; base += GCHUNK) {
        int m = min(GCHUNK, cnt - base);
        __syncthreads();                     // protect sh_idx reuse across chunks
        for (int i = t; i < m; i += 256)
            sh_idx[i] = g_order[s + base + i];
        __syncthreads();

        int r = w;
        for (; r + 64 <= m; r += 64) {       // 8 warps x 8-way unroll
            float4 v[8];
            #pragma unroll
            for (int u = 0; u < 8; u++) {
                size_t p = (size_t)sh_idx[r + u * 8] * 32 + lane;
                v[u] = __ldcs(&x4[p]);
            }
            #pragma unroll
            for (int u = 0; u < 8; u++) {
                acc.x += v[u].x; acc.y += v[u].y;
                acc.z += v[u].z; acc.w += v[u].w;
            }
        }
        for (; r < m; r += 8) {
            float4 v = __ldcs(&x4[(size_t)sh_idx[r] * 32 + lane]);
            acc.x += v.x; acc.y += v.y; acc.z += v.z; acc.w += v.w;
        }
    }

    sh_part[w][lane] = acc;
    __syncthreads();
    if (w == 0) {
        float4 r = sh_part[0][lane];
        #pragma unroll
        for (int wi = 1; wi < 8; wi++) {
            float4 p = sh_part[wi][lane];
            r.x += p.x; r.y += p.y; r.z += p.z; r.w += p.w;
        }
        ((float4*)g_heads[h])[d * 32 + lane] = r;   // partial, no ReLU yet
    }
}

// ---------------------------------------------------------------- F: MLP
// 128 blocks x 256 threads, 8 districts per block. Combines split-4 partials + ReLU.
__global__ void __launch_bounds__(256) k_mlp(
    const float* __restrict__ w1, const float* __restrict__ b1,
    const float* __restrict__ w2, const float* __restrict__ b2,
    float* __restrict__ out)
{
    __shared__ float sh_head[8][DIM];
    __shared__ float sh_h1[8][HID];
    int t = threadIdx.x;
    int base = blockIdx.x * 8;

    for (int idx = t; idx < 8 * DIM; idx += 256) {
        float p = (g_heads[0][base * DIM + idx] + g_heads[1][base * DIM + idx])
                + (g_heads[2][base * DIM + idx] + g_heads[3][base * DIM + idx]);
        sh_head[idx >> 7][idx & 127] = fmaxf(p, 0.f);
    }
    __syncthreads();

    // Phase A: h1 = relu(head @ w1 + b1), thread t = hidden column
    {
        int col = t;
        float acc[8];
        float bb = b1[col];
        #pragma unroll
        for (int r = 0; r < 8; r++) acc[r] = bb;
        #pragma unroll 4
        for (int k = 0; k < DIM; k++) {
            float w = w1[k * HID + col];
            #pragma unroll
            for (int r = 0; r < 8; r++) acc[r] += sh_head[r][k] * w;
        }
        #pragma unroll
        for (int r = 0; r < 8; r++) sh_h1[r][col] = fmaxf(acc[r], 0.f);
    }
    __syncthreads();

    // Phase B: out = h1 @ w2 + b2
    {
        int col = t & 127;
        int r0  = (t >> 7) * 4;
        float acc[4];
        float bb = b2[col];
        #pragma unroll
        for (int r = 0; r < 4; r++) acc[r] = bb;
        #pragma unroll 4
        for (int k = 0; k < HID; k++) {
            float w = w2[k * DIM + col];
            #pragma unroll
            for (int r = 0; r < 4; r++) acc[r] += sh_h1[r0 + r][k] * w;
        }
        #pragma unroll
        for (int r = 0; r < 4; r++)
            out[(size_t)(base + r0 + r) * DIM + col] = acc[r];
    }
}

// ---------------------------------------------------------------- launch
extern "C" void kernel_launch(void* const* d_in, const int* in_sizes, int n_in,
                              void* d_out, int out_size) {
    const float* x    = (const float*)d_in[0];
    const int*   zone = (const int*)d_in[1];
    const float* w1   = (const float*)d_in[2];
    const float* b1   = (const float*)d_in[3];
    const float* w2   = (const float*)d_in[4];
    const float* b2   = (const float*)d_in[5];
    float*       out  = (float*)d_out;
    int n  = in_sizes[1];                // number of nodes (500000, divisible by 4)
    int n4 = n / 4;
    int chunk4 = (n4 + NBLK - 1) / NBLK;

    k_hist       <<<NBLK, 256>>>((const int4*)zone, n4, chunk4);
    k_scan_blocks<<<N_DIST, NBLK>>>();
    k_scan       <<<1, N_DIST>>>();
    k_scatter    <<<NBLK, 256>>>((const int4*)zone, n4, chunk4);
    k_gather     <<<N_DIST * NSPLIT, 256>>>((const float4*)x);
    k_mlp        <<<N_DIST / 8, 256>>>(w1, b1, w2, b2, out);
}

// round 10
// speedup vs baseline: 1.0248x; 1.0248x over previous
#include <cuda_runtime.h>

#define N_DIST 1024
#define DIM    128
#define HID    256
#define MAXN   500000
#define NBLK   512
#define GCHUNK 2048
#define NSPLIT 2
#define NGROUP 128          // 8 districts per group
#define UNITS_PER_GROUP (8 * NSPLIT)

// Scratch (no allocations allowed) — fully rewritten every launch.
__device__ int   g_counts[N_DIST * NBLK];   // [d][b]  (hist writes strided, scan reads coalesced)
__device__ int   g_bcursor[NBLK * N_DIST];  // [b][d]  (scan writes strided, scatter reads coalesced)
__device__ int   g_total[N_DIST];
__device__ int   g_offsets[N_DIST + 1];
__device__ int   g_order[MAXN];
__device__ float g_heads[NSPLIT][N_DIST * DIM];  // split partial heads (pre-ReLU)
__device__ int   g_done[NGROUP];                 // per-group completion counters

// ---------------------------------------------------------------- A: per-block histogram
__global__ void __launch_bounds__(256) k_hist(const int4* __restrict__ zone4, int n4, int chunk4) {
    __shared__ int sh[N_DIST];
    int b = blockIdx.x, t = threadIdx.x;
    if (b == 0 && t < NGROUP) g_done[t] = 0;     // reset completion counters each launch
    for (int i = t; i < N_DIST; i += 256) sh[i] = 0;
    __syncthreads();
    int s = b * chunk4, e = min(n4, s + chunk4);
    for (int i = s + t; i < e; i += 256) {
        int4 z = zone4[i];
        atomicAdd(&sh[z.x], 1);
        atomicAdd(&sh[z.y], 1);
        atomicAdd(&sh[z.z], 1);
        atomicAdd(&sh[z.w], 1);
    }
    __syncthreads();
    for (int i = t; i < N_DIST; i += 256)
        g_counts[i * NBLK + b] = sh[i];          // strided write (hidden)
}

// ---------------------------------------------------------------- B: scan over blocks per district
__global__ void __launch_bounds__(NBLK) k_scan_blocks() {
    __shared__ int s[NBLK];
    int d = blockIdx.x, t = threadIdx.x;
    int c = g_counts[d * NBLK + t];              // coalesced read
    s[t] = c;
    __syncthreads();
    for (int off = 1; off < NBLK; off <<= 1) {
        int add = (t >= off) ? s[t - off] : 0;
        __syncthreads();
        s[t] += add;
        __syncthreads();
    }
    g_bcursor[t * N_DIST + d] = s[t] - c;        // strided write (hidden)
    if (t == NBLK - 1) g_total[d] = s[t];
}

// ---------------------------------------------------------------- C: scatter (inline district scan + smem atomics)
__global__ void __launch_bounds__(256) k_scatter(const int4* __restrict__ zone4, int n4, int chunk4) {
    __shared__ int cur[N_DIST];
    __shared__ int warp_part[8];
    int b = blockIdx.x, t = threadIdx.x;
    int lane = t & 31, w = t >> 5;

    // --- inline exclusive scan of g_total (1024 elems, 4 per thread) ---
    int4 tt = ((const int4*)g_total)[t];
    int mysum = tt.x + tt.y + tt.z + tt.w;
    int inc = mysum;
    #pragma unroll
    for (int o = 1; o < 32; o <<= 1) {
        int v = __shfl_up_sync(0xffffffffu, inc, o);
        if (lane >= o) inc += v;
    }
    if (lane == 31) warp_part[w] = inc;
    __syncthreads();
    if (t == 0) {
        int run = 0;
        #pragma unroll
        for (int i = 0; i < 8; i++) { int v = warp_part[i]; warp_part[i] = run; run += v; }
    }
    __syncthreads();
    int e0 = warp_part[w] + (inc - mysum);       // exclusive prefix of element 4t
    int e1 = e0 + tt.x, e2 = e1 + tt.y, e3 = e2 + tt.z;

    if (b == 0) {                                 // publish offsets for gather
        g_offsets[4 * t + 0] = e0;
        g_offsets[4 * t + 1] = e1;
        g_offsets[4 * t + 2] = e2;
        g_offsets[4 * t + 3] = e3;
        if (t == 255) g_offsets[N_DIST] = e3 + tt.w;
    }

    int4 bc = ((const int4*)g_bcursor)[b * (N_DIST / 4) + t];   // coalesced
    cur[4 * t + 0] = e0 + bc.x;
    cur[4 * t + 1] = e1 + bc.y;
    cur[4 * t + 2] = e2 + bc.z;
    cur[4 * t + 3] = e3 + bc.w;
    __syncthreads();

    // --- scatter ---
    int s = b * chunk4, e = min(n4, s + chunk4);
    for (int i = s + t; i < e; i += 256) {
        int4 z = zone4[i];
        int p0 = atomicAdd(&cur[z.x], 1);
        int p1 = atomicAdd(&cur[z.y], 1);
        int p2 = atomicAdd(&cur[z.z], 1);
        int p3 = atomicAdd(&cur[z.w], 1);
        int i0 = i * 4;
        g_order[p0] = i0;
        g_order[p1] = i0 + 1;
        g_order[p2] = i0 + 2;
        g_order[p3] = i0 + 3;
    }
}

// ---------------------------------------------------------------- D: gather-sum (split-2) + fused MLP
// 2048 blocks: district d = blockIdx>>1, half h = blockIdx&1. 256 threads = 8 warps.
// Last-finishing block of each 8-district group runs the MLP for that group.
__global__ void __launch_bounds__(256) k_gather(
    const float4* __restrict__ x4,
    const float* __restrict__ w1, const float* __restrict__ b1,
    const float* __restrict__ w2, const float* __restrict__ b2,
    float* __restrict__ out)
{
    __shared__ __align__(16) char smem_buf[12 * 1024];
    int*   sh_idx  = (int*)smem_buf;                                  // 8KB (gather)
    float4 (*sh_part)[32] = (float4(*)[32])(smem_buf + 8192);         // 4KB (gather)
    float  (*sh_head)[DIM] = (float(*)[DIM])smem_buf;                 // 4KB (mlp)
    float  (*sh_h1)[HID]   = (float(*)[HID])(smem_buf + 4096);        // 8KB (mlp)
    __shared__ int sh_last;

    int bid = blockIdx.x;
    int d = bid >> 1, h = bid & 1;
    int t = threadIdx.x;
    int w = t >> 5, lane = t & 31;
    int s0 = g_offsets[d], e0 = g_offsets[d + 1];
    int cnt0 = e0 - s0;
    int half = (cnt0 + 1) >> 1;
    int s = s0 + (h ? half : 0);
    int e = h ? e0 : (s0 + half);
    int cnt = e - s;
    float4 acc = make_float4(0.f, 0.f, 0.f, 0.f);

    for (int base = 0; base < cnt; base += GCHUNK) {
        int m = min(GCHUNK, cnt - base);
        __syncthreads();
        for (int i = t; i < m; i += 256)
            sh_idx[i] = g_order[s + base + i];
        __syncthreads();

        int r = w;
        for (; r + 64 <= m; r += 64) {       // 8 warps x 8-way unroll
            float4 v[8];
            #pragma unroll
            for (int u = 0; u < 8; u++) {
                size_t p = (size_t)sh_idx[r + u * 8] * 32 + lane;
                v[u] = __ldcs(&x4[p]);
            }
            #pragma unroll
            for (int u = 0; u < 8; u++) {
                acc.x += v[u].x; acc.y += v[u].y;
                acc.z += v[u].z; acc.w += v[u].w;
            }
        }
        for (; r < m; r += 8) {
            float4 v = __ldcs(&x4[(size_t)sh_idx[r] * 32 + lane]);
            acc.x += v.x; acc.y += v.y; acc.z += v.z; acc.w += v.w;
        }
    }

    sh_part[w][lane] = acc;
    __syncthreads();
    if (w == 0) {
        float4 r = sh_part[0][lane];
        #pragma unroll
        for (int wi = 1; wi < 8; wi++) {
            float4 p = sh_part[wi][lane];
            r.x += p.x; r.y += p.y; r.z += p.z; r.w += p.w;
        }
        ((float4*)g_heads[h])[d * 32 + lane] = r;   // partial, no ReLU yet
        __threadfence();                            // make partial visible before counting
    }
    __syncthreads();

    int grp = d >> 3;
    if (t == 0) {
        int old = atomicAdd(&g_done[grp], 1);
        sh_last = (old == UNITS_PER_GROUP - 1) ? 1 : 0;
    }
    __syncthreads();
    if (!sh_last) return;

    // ---------------- fused MLP for this group's 8 districts ----------------
    int base = grp * 8;
    __syncthreads();   // smem reuse barrier (gather phase fully done)
    for (int idx = t; idx < 8 * DIM; idx += 256) {
        float p = __ldcg(&g_heads[0][base * DIM + idx]) + __ldcg(&g_heads[1][base * DIM + idx]);
        sh_head[idx >> 7][idx & 127] = fmaxf(p, 0.f);
    }
    __syncthreads();

    // Phase A: h1 = relu(head @ w1 + b1), thread t = hidden column
    {
        int col = t;
        float accm[8];
        float bb = b1[col];
        #pragma unroll
        for (int r = 0; r < 8; r++) accm[r] = bb;
        #pragma unroll 4
        for (int k = 0; k < DIM; k++) {
            float wv = w1[k * HID + col];
            #pragma unroll
            for (int r = 0; r < 8; r++) accm[r] += sh_head[r][k] * wv;
        }
        #pragma unroll
        for (int r = 0; r < 8; r++) sh_h1[r][col] = fmaxf(accm[r], 0.f);
    }
    __syncthreads();

    // Phase B: out = h1 @ w2 + b2
    {
        int col = t & 127;
        int r0  = (t >> 7) * 4;
        float accm[4];
        float bb = b2[col];
        #pragma unroll
        for (int r = 0; r < 4; r++) accm[r] = bb;
        #pragma unroll 4
        for (int k = 0; k < HID; k++) {
            float wv = w2[k * DIM + col];
            #pragma unroll
            for (int r = 0; r < 4; r++) accm[r] += sh_h1[r0 + r][k] * wv;
        }
        #pragma unroll
        for (int r = 0; r < 4; r++)
            out[(size_t)(base + r0 + r) * DIM + col] = accm[r];
    }
}

// ---------------------------------------------------------------- launch
extern "C" void kernel_launch(void* const* d_in, const int* in_sizes, int n_in,
                              void* d_out, int out_size) {
    const float* x    = (const float*)d_in[0];
    const int*   zone = (const int*)d_in[1];
    const float* w1   = (const float*)d_in[2];
    const float* b1   = (const float*)d_in[3];
    const float* w2   = (const float*)d_in[4];
    const float* b2   = (const float*)d_in[5];
    float*       out  = (float*)d_out;
    int n  = in_sizes[1];                // number of nodes (500000, divisible by 4)
    int n4 = n / 4;
    int chunk4 = (n4 + NBLK - 1) / NBLK;

    k_hist       <<<NBLK, 256>>>((const int4*)zone, n4, chunk4);
    k_scan_blocks<<<N_DIST, NBLK>>>();
    k_scatter    <<<NBLK, 256>>>((const int4*)zone, n4, chunk4);
    k_gather     <<<N_DIST * NSPLIT, 256>>>((const float4*)x, w1, b1, w2, b2, out);
}